// round 2
// baseline (speedup 1.0000x reference)
#include <cuda_runtime.h>

#define NB   64
#define SEQ  512
#define DIM  64
#define BIGF 1e30f

// Scratch (static device globals — allocation-free per harness rules)
__device__ float g_D[(size_t)NB * SEQ * SEQ];   // 64 MiB distance matrix, row-major per batch
__device__ float g_x2[NB * SEQ];
__device__ float g_y2[NB * SEQ];

// ---------------------------------------------------------------------------
// Kernel 0: row norms. 8 threads per row, 32 rows per 256-thread block.
// ---------------------------------------------------------------------------
__global__ __launch_bounds__(256) void rownorm_kernel(const float* __restrict__ A, int which) {
    int row = blockIdx.x * 32 + (threadIdx.x >> 3);
    int l = threadIdx.x & 7;
    const float4* a = (const float4*)(A + (size_t)row * DIM);
    float4 v1 = __ldg(&a[l * 2]);
    float4 v2 = __ldg(&a[l * 2 + 1]);
    float s = v1.x*v1.x + v1.y*v1.y + v1.z*v1.z + v1.w*v1.w
            + v2.x*v2.x + v2.y*v2.y + v2.z*v2.z + v2.w*v2.w;
    s += __shfl_down_sync(0xffffffffu, s, 4);
    s += __shfl_down_sync(0xffffffffu, s, 2);
    s += __shfl_down_sync(0xffffffffu, s, 1);
    if (l == 0) {
        float* out = which ? g_y2 : g_x2;
        out[row] = s;
    }
}

// ---------------------------------------------------------------------------
// Kernel 1: pairwise squared distances.
// D[b][i][j] = x2[i] + y2[j] - 2 * dot(x_i, y_j)
// 128x128 tile per CTA, 256 threads, 8x8 strided microtile (conflict-free LDS,
// coalesced epilogue stores), BK=32 (two K steps), full fp32.
// ---------------------------------------------------------------------------
#define BM 128
#define BN 128
#define BK 32
#define LDS_STRIDE (BK + 4)   // 36 floats: keeps float4 alignment, breaks bank conflicts

__global__ __launch_bounds__(256) void pairdist_kernel(const float* __restrict__ X,
                                                       const float* __restrict__ Y) {
    __shared__ float Xs[BM * LDS_STRIDE];
    __shared__ float Ys[BN * LDS_STRIDE];

    int b  = blockIdx.z;
    int i0 = blockIdx.y * BM;
    int j0 = blockIdx.x * BN;
    const float* Xb = X + (size_t)b * SEQ * DIM + (size_t)i0 * DIM;
    const float* Yb = Y + (size_t)b * SEQ * DIM + (size_t)j0 * DIM;

    int tid = threadIdx.x;
    int tx = tid & 15;
    int ty = tid >> 4;

    float acc[8][8];
#pragma unroll
    for (int r = 0; r < 8; r++)
#pragma unroll
        for (int c = 0; c < 8; c++) acc[r][c] = 0.0f;

    for (int k0 = 0; k0 < DIM; k0 += BK) {
        __syncthreads();
        // 128 rows x 32 cols = 1024 float4 per tensor; 4 per thread, coalesced
#pragma unroll
        for (int q = 0; q < 4; q++) {
            int idx = tid + q * 256;
            int r  = idx >> 3;
            int c4 = idx & 7;
            float4 xv = __ldg((const float4*)(Xb + (size_t)r * DIM + k0 + c4 * 4));
            float4 yv = __ldg((const float4*)(Yb + (size_t)r * DIM + k0 + c4 * 4));
            *(float4*)(&Xs[r * LDS_STRIDE + c4 * 4]) = xv;
            *(float4*)(&Ys[r * LDS_STRIDE + c4 * 4]) = yv;
        }
        __syncthreads();

#pragma unroll
        for (int d4 = 0; d4 < BK / 4; d4++) {
            float4 a4[8], b4[8];
#pragma unroll
            for (int r = 0; r < 8; r++)
                a4[r] = *(const float4*)(&Xs[(ty + 16 * r) * LDS_STRIDE + d4 * 4]);
#pragma unroll
            for (int c = 0; c < 8; c++)
                b4[c] = *(const float4*)(&Ys[(tx + 16 * c) * LDS_STRIDE + d4 * 4]);
#pragma unroll
            for (int r = 0; r < 8; r++)
#pragma unroll
                for (int c = 0; c < 8; c++) {
                    acc[r][c] += a4[r].x * b4[c].x;
                    acc[r][c] += a4[r].y * b4[c].y;
                    acc[r][c] += a4[r].z * b4[c].z;
                    acc[r][c] += a4[r].w * b4[c].w;
                }
        }
    }

    // Epilogue: D = x2 + y2 - 2*acc. Strided microtile -> coalesced stores.
    float yn[8];
#pragma unroll
    for (int c = 0; c < 8; c++) yn[c] = g_y2[b * SEQ + j0 + tx + 16 * c];
    float* Db = g_D + (size_t)b * SEQ * SEQ;
#pragma unroll
    for (int r = 0; r < 8; r++) {
        int i = i0 + ty + 16 * r;
        float xn = g_x2[b * SEQ + i];
#pragma unroll
        for (int c = 0; c < 8; c++) {
            int j = j0 + tx + 16 * c;
            Db[(size_t)i * SEQ + j] = xn + yn[c] - 2.0f * acc[r][c];
        }
    }
}

// ---------------------------------------------------------------------------
// Kernel 2: soft-DTW anti-diagonal wavefront DP.
// One CTA per batch, thread i owns row i. R buffers rotate over 3 SMEM arrays.
// Thread i walks D row i sequentially -> float4 register prefetch pipeline.
// softmin(a,b,c) = m - log(exp(m-a)+exp(m-b)+exp(m-c)), m = min (one term = 1).
// ---------------------------------------------------------------------------
__global__ __launch_bounds__(SEQ) void softdtw_kernel(float* __restrict__ out) {
    int b = blockIdx.x;
    int i = threadIdx.x;

    __shared__ float R[3][SEQ + 2];
    // init all buffers to BIG (index 0 and SEQ+1 are permanent pads)
    for (int k = i; k < SEQ + 2; k += SEQ) {
        R[0][k] = BIGF; R[1][k] = BIGF; R[2][k] = BIGF;
    }
    __syncthreads();

    const float4* row4 = (const float4*)(g_D + (size_t)b * SEQ * SEQ + (size_t)i * SEQ);
    float4 bufA = __ldg(&row4[0]);
    float4 bufB = __ldg(&row4[1]);
    int nxt = 2;

    int pp2 = 0, pp1 = 1, pc = 2;

    for (int p = 0; p < 2 * SEQ - 1; ++p) {
        int j = p - i;
        float val = BIGF;
        if (j >= 0 && j < SEQ) {
            int m = j & 3;
            float d = (m == 0) ? bufA.x : (m == 1) ? bufA.y : (m == 2) ? bufA.z : bufA.w;
            if (m == 3) {
                bufA = bufB;
                if (nxt < SEQ / 4) bufB = __ldg(&row4[nxt]);
                nxt++;
            }
            // predecessors: a = R(i-1,j-1), u = R(i-1,j), l = R(i,j-1)
            float a = (p == 0) ? 0.0f : R[pp2][i];   // (0,0) boundary: diag term = 0
            float u = R[pp1][i];
            float l = R[pp1][i + 1];
            float mn = fminf(a, fminf(u, l));
            float s = __expf(mn - a) + __expf(mn - u) + __expf(mn - l);
            val = d + mn - __logf(s);
        }
        R[pc][i + 1] = val;
        if (p == 2 * SEQ - 2 && i == SEQ - 1) out[b] = val;
        __syncthreads();
        int t = pp2; pp2 = pp1; pp1 = pc; pc = t;
    }
}

// ---------------------------------------------------------------------------
extern "C" void kernel_launch(void* const* d_in, const int* in_sizes, int n_in,
                              void* d_out, int out_size) {
    const float* x = (const float*)d_in[0];
    const float* y = (const float*)d_in[1];
    float* out = (float*)d_out;

    rownorm_kernel<<<NB * SEQ / 32, 256>>>(x, 0);
    rownorm_kernel<<<NB * SEQ / 32, 256>>>(y, 1);

    dim3 g(SEQ / BN, SEQ / BM, NB);
    pairdist_kernel<<<g, 256>>>(x, y);

    softdtw_kernel<<<NB, SEQ>>>(out);
}

// round 3
// speedup vs baseline: 1.6100x; 1.6100x over previous
#include <cuda_runtime.h>

#define NB   64
#define SEQ  512
#define DIM  64
#define BIGF 1e30f

typedef unsigned long long u64;

// Scratch (static device globals — allocation-free per harness rules)
__device__ float g_D[(size_t)NB * SEQ * SEQ];   // 64 MiB distance matrix, row-major per batch
__device__ float g_x2[NB * SEQ];
__device__ float g_y2[NB * SEQ];

// ---------------------------------------------------------------------------
// f32x2 packed helpers (sm_103a FFMA2 path — PTX only, ptxas won't auto-fuse)
// ---------------------------------------------------------------------------
__device__ __forceinline__ u64 ffma2(u64 a, u64 b, u64 c) {
    u64 d;
    asm("fma.rn.f32x2 %0, %1, %2, %3;" : "=l"(d) : "l"(a), "l"(b), "l"(c));
    return d;
}
__device__ __forceinline__ u64 pack2(float lo, float hi) {
    u64 d;
    asm("mov.b64 %0, {%1, %2};" : "=l"(d) : "f"(lo), "f"(hi));
    return d;
}
__device__ __forceinline__ float2 unpack2(u64 v) {
    float2 r;
    asm("mov.b64 {%0, %1}, %2;" : "=f"(r.x), "=f"(r.y) : "l"(v));
    return r;
}

// ---------------------------------------------------------------------------
// Kernel 0: row norms. 8 threads per row, 32 rows per 256-thread block.
// ---------------------------------------------------------------------------
__global__ __launch_bounds__(256) void rownorm_kernel(const float* __restrict__ A, int which) {
    int row = blockIdx.x * 32 + (threadIdx.x >> 3);
    int l = threadIdx.x & 7;
    const float4* a = (const float4*)(A + (size_t)row * DIM);
    float4 v1 = __ldg(&a[l * 2]);
    float4 v2 = __ldg(&a[l * 2 + 1]);
    float s = v1.x*v1.x + v1.y*v1.y + v1.z*v1.z + v1.w*v1.w
            + v2.x*v2.x + v2.y*v2.y + v2.z*v2.z + v2.w*v2.w;
    s += __shfl_down_sync(0xffffffffu, s, 4);
    s += __shfl_down_sync(0xffffffffu, s, 2);
    s += __shfl_down_sync(0xffffffffu, s, 1);
    if (l == 0) {
        float* out = which ? g_y2 : g_x2;
        out[row] = s;
    }
}

// ---------------------------------------------------------------------------
// Kernel 1: pairwise squared distances with packed f32x2 FFMA2.
// D[b][i][j] = x2[i] + y2[j] - 2 * dot(x_i, y_j)
// 128x128 tile per CTA, 256 threads, 8 rows x 8 cols per thread.
// Columns packed in pairs (c=2c2, 2c2+1) -> 4 u64 accumulators per row.
// SMEM layouts feed FFMA2 operands directly from LDS.64:
//   Xs2[row][k][2]   : each x value duplicated (x,x)
//   Ys2[pr][k][2]    : column pair (y_{r0}, y_{r1}), r1 = r0 + 16
// ---------------------------------------------------------------------------
#define BM 128
#define BN 128
#define BK 16
#define STRX 34           // words per Xs2 row  (16*2 + 2 pad), *4B multiple of 8
#define STRY 34           // words per Ys2 row  -> 2*tx bank stride, conflict-free LDS.64

__global__ __launch_bounds__(256, 2) void pairdist_kernel(const float* __restrict__ X,
                                                          const float* __restrict__ Y) {
    __shared__ float Xs2[BM * STRX];   // 17.4 KB
    __shared__ float Ys2[64 * STRY];   //  8.7 KB

    int b  = blockIdx.z;
    int i0 = blockIdx.y * BM;
    int j0 = blockIdx.x * BN;
    const float* Xb = X + (size_t)b * SEQ * DIM + (size_t)i0 * DIM;
    const float* Yb = Y + (size_t)b * SEQ * DIM + (size_t)j0 * DIM;

    int tid = threadIdx.x;
    int tx = tid & 15;     // column-group base
    int ty = tid >> 4;     // row-group base

    u64 acc2[8][4];
#pragma unroll
    for (int r = 0; r < 8; r++)
#pragma unroll
        for (int c2 = 0; c2 < 4; c2++) acc2[r][c2] = 0ull;

    for (int k0 = 0; k0 < DIM; k0 += BK) {
        __syncthreads();
        // 128 rows x 16 cols per tensor = 512 float4; 2 per thread per tensor.
#pragma unroll
        for (int q = 0; q < 2; q++) {
            int idx = tid + q * 256;
            int r  = idx >> 2;      // 0..127
            int c4 = idx & 3;       // k quad
            float4 xv = __ldg((const float4*)(Xb + (size_t)r * DIM + k0 + c4 * 4));
            float4 yv = __ldg((const float4*)(Yb + (size_t)r * DIM + k0 + c4 * 4));
            // X duplicated: STS.64 of (x,x)
            u64* xs = (u64*)&Xs2[r * STRX + c4 * 8];
            xs[0] = pack2(xv.x, xv.x);
            xs[1] = pack2(xv.y, xv.y);
            xs[2] = pack2(xv.z, xv.z);
            xs[3] = pack2(xv.w, xv.w);
            // Y column-pair interleave: pr = (r&15) + 16*(r>>5), slot = (r>>4)&1
            int pr   = (r & 15) + 16 * (r >> 5);
            int slot = (r >> 4) & 1;
            float* ys = &Ys2[pr * STRY + c4 * 8 + slot];
            ys[0] = yv.x; ys[2] = yv.y; ys[4] = yv.z; ys[6] = yv.w;
        }
        __syncthreads();

#pragma unroll
        for (int k = 0; k < BK; k++) {
            u64 bb[4];
#pragma unroll
            for (int c2 = 0; c2 < 4; c2++)
                bb[c2] = *(const u64*)&Ys2[(tx + 16 * c2) * STRY + k * 2];
#pragma unroll
            for (int r = 0; r < 8; r++) {
                u64 aa = *(const u64*)&Xs2[(ty + 16 * r) * STRX + k * 2];
#pragma unroll
                for (int c2 = 0; c2 < 4; c2++)
                    acc2[r][c2] = ffma2(aa, bb[c2], acc2[r][c2]);
            }
        }
    }

    // Epilogue: D = x2 + y2 - 2*acc. Column pairs (2c2, 2c2+1) -> j = j0+tx+16c.
    float yn[8];
#pragma unroll
    for (int c = 0; c < 8; c++) yn[c] = g_y2[b * SEQ + j0 + tx + 16 * c];
    float* Db = g_D + (size_t)b * SEQ * SEQ;
#pragma unroll
    for (int r = 0; r < 8; r++) {
        int i = i0 + ty + 16 * r;
        float xn = g_x2[b * SEQ + i];
#pragma unroll
        for (int c2 = 0; c2 < 4; c2++) {
            float2 d2 = unpack2(acc2[r][c2]);
            int jA = j0 + tx + 16 * (2 * c2);
            int jB = j0 + tx + 16 * (2 * c2 + 1);
            Db[(size_t)i * SEQ + jA] = xn + yn[2 * c2]     - 2.0f * d2.x;
            Db[(size_t)i * SEQ + jB] = xn + yn[2 * c2 + 1] - 2.0f * d2.y;
        }
    }
}

// ---------------------------------------------------------------------------
// Kernel 2: soft-DTW wavefront, barrier-free.
// Thread i owns row i. Per diagonal p:
//   u = val(i-1,p-1) via shfl_up, a = val(i-1,p-2) = previous shuffle (register),
//   l = val(i,p-1) = own register.
// Warp boundaries: lane 31 publishes val via volatile 32-bit STS into a
// canary-initialized slot array; next warp's whole warp polls the one slot it
// needs (broadcast LDS). Warps self-pipeline with a 1-diagonal skew; each warp
// runs only its live window of 543 diagonals.
// softmin via sort: lo=min(u,l), hi=max(u,l), mn=min(a,lo), m1=max(a,lo)
//   -> sum = 1 + exp(mn-m1) + exp(mn-hi)   (2 EX2 + 1 LG2)
// ---------------------------------------------------------------------------
#define CANARY 0xFFC00001u   // NaN bit pattern never produced by the DP

__global__ __launch_bounds__(SEQ) void softdtw_kernel(float* __restrict__ out) {
    int b    = blockIdx.x;
    int tid  = threadIdx.x;
    int w    = tid >> 5;
    int lane = tid & 31;
    int i    = tid;

    __shared__ unsigned int bnd[15 * SEQ];   // 30 KB boundary history
    for (int k = tid; k < 15 * SEQ; k += SEQ) bnd[k] = CANARY;
    __syncthreads();

    const float4* row4 = (const float4*)(g_D + (size_t)b * SEQ * SEQ + (size_t)i * SEQ);
    float4 bufA = __ldg(row4);
    float4 bufB = __ldg(row4 + 1);
    int nxt = 2;

    float val = BIGF;    // val(i, p-1)
    float shp = BIGF;    // val(i-1, p-2)  (previous shuffle result)
    float bu  = BIGF;    // lane0: boundary val(i-1, p-2)

    volatile unsigned int* rslot = &bnd[(w > 0 ? (w - 1) : 0) * SEQ];
    volatile unsigned int* wslot = &bnd[(w < 15 ? w : 0) * SEQ];

    int p0   = w * 32;
    int pend = p0 + 543;   // warp live window: exactly 543 diagonals

    for (int p = p0; p < pend; ++p) {
        int j = p - i;
        float sh = __shfl_up_sync(0xffffffffu, val, 1);
        float a = shp;
        float u = sh;
        shp = sh;

        int idx = p - p0;                    // lane0's j; warp-uniform
        if (w > 0 && idx < SEQ) {
            unsigned int v = rslot[idx];     // whole warp polls same word (broadcast)
            while (v == CANARY) v = rslot[idx];
            float nb = __uint_as_float(v);
            if (lane == 0) { a = bu; u = nb; }
            bu = nb;
        }
        if (w == 0 && lane == 0) {
            u = BIGF;
            a = (p == 0) ? 0.0f : BIGF;
        }

        if (j >= 0 && j < SEQ) {
            int m = j & 3;
            float d = (m == 0) ? bufA.x : (m == 1) ? bufA.y : (m == 2) ? bufA.z : bufA.w;
            if (m == 3) {
                bufA = bufB;
                if (nxt < SEQ / 4) bufB = __ldg(row4 + nxt);
                nxt++;
            }
            float l  = val;
            float lo = fminf(u, l), hi = fmaxf(u, l);
            float mn = fminf(a, lo), m1 = fmaxf(a, lo);
            float s  = 1.0f + __expf(mn - m1) + __expf(mn - hi);
            val = d + (mn - __logf(s));
            if (lane == 31 && w < 15) wslot[j] = __float_as_uint(val);
            if (tid == SEQ - 1 && j == SEQ - 1) out[b] = val;
        }
    }
}

// ---------------------------------------------------------------------------
extern "C" void kernel_launch(void* const* d_in, const int* in_sizes, int n_in,
                              void* d_out, int out_size) {
    const float* x = (const float*)d_in[0];
    const float* y = (const float*)d_in[1];
    float* out = (float*)d_out;

    rownorm_kernel<<<NB * SEQ / 32, 256>>>(x, 0);
    rownorm_kernel<<<NB * SEQ / 32, 256>>>(y, 1);

    dim3 g(SEQ / BN, SEQ / BM, NB);
    pairdist_kernel<<<g, 256>>>(x, y);

    softdtw_kernel<<<NB, SEQ>>>(out);
}